// round 12
// baseline (speedup 1.0000x reference)
#include <cuda_runtime.h>
#include <math.h>

#define BATCH    4096
#define T        80
#define VOCAB    10000
#define EMB      100
#define H        256
#define HS       36          // padded SMEM stride for state tiles
#define KC       32          // k-chunk for streamed weight tiles
#define M2       32          // batch rows per block
#define NTHREADS 256

typedef unsigned long long u64;

// Precomputed embW[v][n] = b1[n] + sum_k emb[v][k] * W1[k][n]   (10.24 MB, L2-resident)
__device__ float g_embW[(size_t)VOCAB * H];

__device__ __forceinline__ u64 ffma2(u64 a, u64 b, u64 c) {
    u64 d;
    asm("fma.rn.f32x2 %0, %1, %2, %3;" : "=l"(d) : "l"(a), "l"(b), "l"(c));
    return d;
}
__device__ __forceinline__ u64 splat2(float x) {
    u64 d; asm("mov.b64 %0, {%1, %1};" : "=l"(d) : "f"(x)); return d;
}
__device__ __forceinline__ u64 pack2(float lo, float hi) {
    u64 d; asm("mov.b64 %0, {%1, %2};" : "=l"(d) : "f"(lo), "f"(hi)); return d;
}
__device__ __forceinline__ void unpack2(u64 p, float& lo, float& hi) {
    asm("mov.b64 {%0, %1}, %2;" : "=f"(lo), "=f"(hi) : "l"(p));
}
// fast tanh via expf: rel err ~1e-6, ~6 instrs
__device__ __forceinline__ float tanh_e(float x) {
    float e = __expf(-2.f * fabsf(x));
    float r = __fdividef(1.f - e, 1.f + e);
    return copysignf(r, x);
}

// ============================================================================
// embW precompute: grid ceil(VOCAB/32), 256 thr. embW = b1 + emb @ W1.
// ============================================================================
__global__ __launch_bounds__(NTHREADS, 1)
void embw_kernel(const float* __restrict__ emb, const float* __restrict__ W1,
                 const float* __restrict__ b1)
{
    extern __shared__ float sm[];
    float* W1s = sm;                 // EMB*H  = 25600 floats
    float* xs  = W1s + EMB * H;      // EMB*HS =  3600 floats

    const int tid = threadIdx.x;
    const int ty = tid >> 6, tx = tid & 63;
    const int r0 = ty * 8, c0 = tx * 4;
    const int v0 = blockIdx.x * M2;

    // W1 -> smem (6400 float4, 25/thread)
#pragma unroll
    for (int j = 0; j < (EMB * H / 4) / NTHREADS; ++j)
        ((float4*)W1s)[tid + j * NTHREADS] = ((const float4*)W1)[tid + j * NTHREADS];
    // zero xs (covers out-of-vocab tail rows)
    for (int i = tid; i < EMB * HS; i += NTHREADS) xs[i] = 0.f;
    __syncthreads();
    // gather emb rows k-major
    for (int i = tid; i < M2 * (EMB / 4); i += NTHREADS) {
        int r = i / (EMB / 4), q = i % (EMB / 4);
        int v = v0 + r;
        if (v < VOCAB) {
            float4 x = ((const float4*)emb)[v * (EMB / 4) + q];
            xs[(4 * q + 0) * HS + r] = x.x;
            xs[(4 * q + 1) * HS + r] = x.y;
            xs[(4 * q + 2) * HS + r] = x.z;
            xs[(4 * q + 3) * HS + r] = x.w;
        }
    }
    const float4 b1v = ((const float4*)b1)[tx];
    __syncthreads();

    u64 acc[4][4];
    const u64 bp[4] = { splat2(b1v.x), splat2(b1v.y), splat2(b1v.z), splat2(b1v.w) };
#pragma unroll
    for (int p = 0; p < 4; ++p)
#pragma unroll
        for (int j = 0; j < 4; ++j) acc[p][j] = bp[j];

#pragma unroll 4
    for (int k = 0; k < EMB; ++k) {
        float4 a0 = *(const float4*)&xs[k * HS + r0];
        float4 a1 = *(const float4*)&xs[k * HS + r0 + 4];
        float4 b  = *(const float4*)&W1s[k * H + c0];
        u64 ap[4] = { pack2(a0.x, a0.y), pack2(a0.z, a0.w),
                      pack2(a1.x, a1.y), pack2(a1.z, a1.w) };
        u64 bb[4] = { splat2(b.x), splat2(b.y), splat2(b.z), splat2(b.w) };
#pragma unroll
        for (int p = 0; p < 4; ++p)
#pragma unroll
            for (int j = 0; j < 4; ++j)
                acc[p][j] = ffma2(ap[p], bb[j], acc[p][j]);
    }
    // store rows v0+r0 .. v0+r0+7
#pragma unroll
    for (int i = 0; i < 8; ++i) {
        int v = v0 + r0 + i;
        if (v < VOCAB) {
            float t0, t1, t2, t3, lo, hi;
            unpack2(acc[i >> 1][0], lo, hi); t0 = (i & 1) ? hi : lo;
            unpack2(acc[i >> 1][1], lo, hi); t1 = (i & 1) ? hi : lo;
            unpack2(acc[i >> 1][2], lo, hi); t2 = (i & 1) ? hi : lo;
            unpack2(acc[i >> 1][3], lo, hi); t3 = (i & 1) ? hi : lo;
            *(float4*)&g_embW[(size_t)v * H + c0] = make_float4(t0, t1, t2, t3);
        }
    }
}

// ============================================================================
// Recurrent GEMM: acc += hs(k-major [256][HS]) @ Wg([256][256] row-major).
// Exactly 8 KC=32 tiles, double-buffered, ONE sync per tile (R4-proven).
// ============================================================================
__device__ __forceinline__ void gemm_stream(
    const float* __restrict__ Wg, const float* __restrict__ hs,
    float* __restrict__ wbuf, u64 acc[4][4], int tid, int r0, int c0)
{
    const float4* W4 = (const float4*)Wg;
    float4 pre[8];
#pragma unroll
    for (int j = 0; j < 8; ++j) pre[j] = W4[tid + j * NTHREADS];

#pragma unroll 1
    for (int kt = 0; kt < H / KC; ++kt) {
        float* buf = wbuf + (kt & 1) * (KC * H);
#pragma unroll
        for (int j = 0; j < 8; ++j)
            ((float4*)buf)[tid + j * NTHREADS] = pre[j];
        if (kt + 1 < H / KC) {
#pragma unroll
            for (int j = 0; j < 8; ++j)
                pre[j] = W4[(kt + 1) * (KC * H / 4) + tid + j * NTHREADS];
        }
        __syncthreads();
        const float* hk = hs + kt * KC * HS;
#pragma unroll 8
        for (int kk = 0; kk < KC; ++kk) {
            float4 a0 = *(const float4*)&hk[kk * HS + r0];
            float4 a1 = *(const float4*)&hk[kk * HS + r0 + 4];
            float4 b  = *(const float4*)&buf[kk * H + c0];
            u64 ap[4] = { pack2(a0.x, a0.y), pack2(a0.z, a0.w),
                          pack2(a1.x, a1.y), pack2(a1.z, a1.w) };
            u64 bb[4] = { splat2(b.x), splat2(b.y), splat2(b.z), splat2(b.w) };
#pragma unroll
            for (int p = 0; p < 4; ++p)
#pragma unroll
                for (int j = 0; j < 4; ++j)
                    acc[p][j] = ffma2(ap[p], bb[j], acc[p][j]);
        }
    }
}

__device__ __forceinline__ void tanh_store(u64 acc[4][4], float* __restrict__ st,
                                           int r0, int c0)
{
    float t[8][4];
#pragma unroll
    for (int p = 0; p < 4; ++p)
#pragma unroll
        for (int j = 0; j < 4; ++j) {
            float lo, hi; unpack2(acc[p][j], lo, hi);
            t[2 * p][j] = tanh_e(lo); t[2 * p + 1][j] = tanh_e(hi);
        }
#pragma unroll
    for (int j = 0; j < 4; ++j)
#pragma unroll
        for (int ii = 0; ii < 2; ++ii)
            *(float4*)&st[(c0 + j) * HS + r0 + 4 * ii] =
                make_float4(t[4 * ii + 0][j], t[4 * ii + 1][j],
                            t[4 * ii + 2][j], t[4 * ii + 3][j]);
}

__global__ __launch_bounds__(NTHREADS, 1)
void rnn_fused_kernel(const int*   __restrict__ inputs,
                      const float* __restrict__ U1,
                      const float* __restrict__ W2,
                      const float* __restrict__ U2,
                      const float* __restrict__ b2,
                      float*       __restrict__ out)
{
    extern __shared__ float sm[];
    float* h1   = sm;                    // H*HS   = 9216 floats
    float* h2   = h1 + H * HS;           // H*HS   = 9216
    float* wbuf = h2 + H * HS;           // 2*KC*H = 16384
    int*   toks = (int*)(wbuf + 2 * KC * H);   // M2*T = 2560 ints

    const int tid = threadIdx.x;
    const int ty = tid >> 6, tx = tid & 63;
    const int r0 = ty * 8, c0 = tx * 4;
    const int bb = blockIdx.x * M2;

    for (int i = tid; i < 2 * H * HS; i += NTHREADS) h1[i] = 0.f;
    for (int i = tid; i < M2 * T; i += NTHREADS)
        toks[i] = inputs[(bb + i / T) * T + (i % T)];

    const float4 b2v = ((const float4*)b2)[tx];
    const u64 b2p[4] = { splat2(b2v.x), splat2(b2v.y), splat2(b2v.z), splat2(b2v.w) };
    __syncthreads();

#pragma unroll 1
    for (int t = 0; t < T; ++t) {
        // ---- layer 1: acc = embW[tok] (has b1 baked) + h1_old@U1 ----
        float4 xv[8];
#pragma unroll
        for (int i = 0; i < 8; ++i) {
            int tok = toks[(r0 + i) * T + t];
            xv[i] = *(const float4*)&g_embW[(size_t)tok * H + c0];
        }
        u64 acc[4][4];
#pragma unroll
        for (int p = 0; p < 4; ++p) {
            const float* lo = (const float*)&xv[2 * p];
            const float* hi = (const float*)&xv[2 * p + 1];
#pragma unroll
            for (int j = 0; j < 4; ++j) acc[p][j] = pack2(lo[j], hi[j]);
        }
        gemm_stream(U1, h1, wbuf, acc, tid, r0, c0);

        __syncthreads();                 // all threads done reading old h1
        tanh_store(acc, h1, r0, c0);
        __syncthreads();                 // new h1 visible

        // ---- layer 2: acc2 = b2 + h1_new@W2 + h2_old@U2 ----
        u64 acc2[4][4];
#pragma unroll
        for (int p = 0; p < 4; ++p)
#pragma unroll
            for (int j = 0; j < 4; ++j) acc2[p][j] = b2p[j];
        gemm_stream(W2, h1, wbuf, acc2, tid, r0, c0);
        gemm_stream(U2, h2, wbuf, acc2, tid, r0, c0);

        __syncthreads();                 // all threads done reading old h2
        if (t == T - 1) {
#pragma unroll
            for (int i = 0; i < 8; ++i) {
                float v[4];
#pragma unroll
                for (int j = 0; j < 4; ++j) {
                    float lo, hi; unpack2(acc2[i >> 1][j], lo, hi);
                    float x = tanh_e((i & 1) ? hi : lo);
                    v[j] = __fdividef(1.f, 1.f + __expf(-x));
                }
                *(float4*)&out[(bb + r0 + i) * H + c0] =
                    make_float4(v[0], v[1], v[2], v[3]);
            }
        } else {
            tanh_store(acc2, h2, r0, c0);
            // publish of new h2 is covered by next step's gemm tile-syncs
        }
    }
}

extern "C" void kernel_launch(void* const* d_in, const int* in_sizes, int n_in,
                              void* d_out, int out_size)
{
    const int*   inputs = (const int*)  d_in[0];
    const float* emb    = (const float*)d_in[1];
    const float* W1     = (const float*)d_in[2];
    const float* U1     = (const float*)d_in[3];
    const float* b1     = (const float*)d_in[4];
    const float* W2     = (const float*)d_in[5];
    const float* U2     = (const float*)d_in[6];
    const float* b2     = (const float*)d_in[7];
    float* out = (float*)d_out;

    const int smem_embw = (EMB * H + EMB * HS) * (int)sizeof(float);            // 116800
    const int smem_main = (2 * H * HS + 2 * KC * H + M2 * T) * (int)sizeof(float); // 149504

    cudaFuncSetAttribute(embw_kernel,
                         cudaFuncAttributeMaxDynamicSharedMemorySize, smem_embw);
    cudaFuncSetAttribute(rnn_fused_kernel,
                         cudaFuncAttributeMaxDynamicSharedMemorySize, smem_main);

    embw_kernel<<<(VOCAB + M2 - 1) / M2, NTHREADS, smem_embw>>>(emb, W1, b1);
    rnn_fused_kernel<<<BATCH / M2, NTHREADS, smem_main>>>(
        inputs, U1, W2, U2, b2, out);
}

// round 14
// speedup vs baseline: 1.5796x; 1.5796x over previous
#include <cuda_runtime.h>
#include <cuda_bf16.h>
#include <cstdint>
#include <math.h>

#define BATCH 4096
#define T     80
#define VOCAB 10000
#define EMB   100
#define H     256
#define HS    36
#define M2    32
#define NTH   256
#define SA    264          // state array k-stride (bf16): 528B rows, odd 16B-phase -> conflict-free ldmatrix
#define WS    40           // weight tile k-stride (bf16): 80B rows, odd phase -> conflict-free

typedef uint32_t u32; typedef unsigned long long u64;

__device__ float g_embW[(size_t)VOCAB * H];
__device__ __nv_bfloat16 g_wbf[3][2][H * H];   // [U1,W2,U2][hi,lo][n*256+k] (transposed)

__device__ __forceinline__ u32 smem_u32(const void* p) {
    u32 a; asm("{ .reg .u64 t; cvta.to.shared.u64 t, %1; cvt.u32.u64 %0, t; }" : "=r"(a) : "l"(p));
    return a;
}
__device__ __forceinline__ float tanh_e(float x) {
    float e = __expf(-2.f * fabsf(x));
    return copysignf(__fdividef(1.f - e, 1.f + e), x);
}
__device__ __forceinline__ u64 ffma2(u64 a, u64 b, u64 c) {
    u64 d; asm("fma.rn.f32x2 %0, %1, %2, %3;" : "=l"(d) : "l"(a), "l"(b), "l"(c)); return d;
}
__device__ __forceinline__ u64 splat2(float x) { u64 d; asm("mov.b64 %0, {%1, %1};" : "=l"(d) : "f"(x)); return d; }
__device__ __forceinline__ u64 pack2(float lo, float hi) { u64 d; asm("mov.b64 %0, {%1, %2};" : "=l"(d) : "f"(lo), "f"(hi)); return d; }
__device__ __forceinline__ void unpack2(u64 p, float& lo, float& hi) { asm("mov.b64 {%0, %1}, %2;" : "=f"(lo), "=f"(hi) : "l"(p)); }

#define LDSM4(r0, r1, r2, r3, a) \
    asm volatile("ldmatrix.sync.aligned.m8n8.x4.shared.b16 {%0,%1,%2,%3}, [%4];" \
                 : "=r"(r0), "=r"(r1), "=r"(r2), "=r"(r3) : "r"(a))
#define MMA(c, a, b0, b1) \
    asm volatile("mma.sync.aligned.m16n8k16.row.col.f32.bf16.bf16.f32 " \
                 "{%0,%1,%2,%3}, {%4,%5,%6,%7}, {%8,%9}, {%0,%1,%2,%3};" \
                 : "+f"((c)[0]), "+f"((c)[1]), "+f"((c)[2]), "+f"((c)[3]) \
                 : "r"((a)[0]), "r"((a)[1]), "r"((a)[2]), "r"((a)[3]), "r"(b0), "r"(b1))

// ---- prep: W -> bf16 hi/lo, transposed to [n][k] ----
__global__ void prep_weights(const float* __restrict__ U1, const float* __restrict__ W2,
                             const float* __restrict__ U2)
{
    int idx = blockIdx.x * blockDim.x + threadIdx.x;
    if (idx >= 3 * H * H) return;
    int which = idx / (H * H), r = idx % (H * H);
    int k = r >> 8, n = r & 255;
    const float* s = which == 0 ? U1 : which == 1 ? W2 : U2;
    float v = s[k * H + n];
    __nv_bfloat16 hb = __float2bfloat16(v);
    g_wbf[which][0][n * H + k] = hb;
    g_wbf[which][1][n * H + k] = __float2bfloat16(v - __bfloat162float(hb));
}

// ---- embW = b1 + emb @ W1 (R10-proven, fp32) ----
__global__ __launch_bounds__(NTH, 1)
void embw_kernel(const float* __restrict__ emb, const float* __restrict__ W1,
                 const float* __restrict__ b1)
{
    extern __shared__ float sm[];
    float* W1s = sm; float* xs = W1s + EMB * H;
    const int tid = threadIdx.x, ty = tid >> 6, tx = tid & 63;
    const int r0 = ty * 8, c0 = tx * 4, v0 = blockIdx.x * 32;
#pragma unroll
    for (int j = 0; j < (EMB * H / 4) / NTH; ++j)
        ((float4*)W1s)[tid + j * NTH] = ((const float4*)W1)[tid + j * NTH];
    for (int i = tid; i < EMB * HS; i += NTH) xs[i] = 0.f;
    __syncthreads();
    for (int i = tid; i < 32 * (EMB / 4); i += NTH) {
        int r = i / (EMB / 4), q = i % (EMB / 4), v = v0 + r;
        if (v < VOCAB) {
            float4 x = ((const float4*)emb)[v * (EMB / 4) + q];
            xs[(4 * q + 0) * HS + r] = x.x; xs[(4 * q + 1) * HS + r] = x.y;
            xs[(4 * q + 2) * HS + r] = x.z; xs[(4 * q + 3) * HS + r] = x.w;
        }
    }
    const float4 b1v = ((const float4*)b1)[tx];
    __syncthreads();
    u64 acc[4][4];
    const u64 bp[4] = { splat2(b1v.x), splat2(b1v.y), splat2(b1v.z), splat2(b1v.w) };
#pragma unroll
    for (int p = 0; p < 4; ++p)
#pragma unroll
        for (int j = 0; j < 4; ++j) acc[p][j] = bp[j];
#pragma unroll 4
    for (int k = 0; k < EMB; ++k) {
        float4 a0 = *(const float4*)&xs[k * HS + r0];
        float4 a1 = *(const float4*)&xs[k * HS + r0 + 4];
        float4 b  = *(const float4*)&W1s[k * H + c0];
        u64 ap[4] = { pack2(a0.x, a0.y), pack2(a0.z, a0.w), pack2(a1.x, a1.y), pack2(a1.z, a1.w) };
        u64 bb[4] = { splat2(b.x), splat2(b.y), splat2(b.z), splat2(b.w) };
#pragma unroll
        for (int p = 0; p < 4; ++p)
#pragma unroll
            for (int j = 0; j < 4; ++j) acc[p][j] = ffma2(ap[p], bb[j], acc[p][j]);
    }
#pragma unroll
    for (int i = 0; i < 8; ++i) {
        int v = v0 + r0 + i;
        if (v < VOCAB) {
            float o[4];
#pragma unroll
            for (int j = 0; j < 4; ++j) { float lo, hi; unpack2(acc[i >> 1][j], lo, hi); o[j] = (i & 1) ? hi : lo; }
            *(float4*)&g_embW[(size_t)v * H + c0] = make_float4(o[0], o[1], o[2], o[3]);
        }
    }
}

// ---- HMMA GEMM: c[2][4][4] += state(A, [32][256] bf16 hi/lo) @ W^T ([n][k] hi/lo)
// 8 k-chunks of 32, double-buffered weight tiles, ONE sync per chunk.
__device__ __forceinline__ void gemm_mma(
    const __nv_bfloat16* __restrict__ Whi, const __nv_bfloat16* __restrict__ Wlo,
    u32 aHi, u32 aLo, float4* wb4, u32 wbu,
    float (&c)[2][4][4], int tid, int lane, int w)
{
    const float4* S0 = (const float4*)Whi;
    const float4* S1 = (const float4*)Wlo;
    const int grp = lane >> 3, lr = lane & 7;
    const u32 aoff = (u32)(((lr + (grp & 1) * 8) * SA + (grp >> 1) * 8) * 2);
    const u32 boff = (u32)(((lr + (grp >> 1) * 8) * WS + (grp & 1) * 8) * 2);
    int so[4], dofs[4];
#pragma unroll
    for (int j = 0; j < 4; ++j) {
        int idx = tid + j * NTH;
        so[j]  = (idx >> 2) * 32 + (idx & 3);   // src float4 in [n][256] row
        dofs[j] = (idx >> 2) * 5 + (idx & 3);   // dst float4 in [n][WS] tile
    }
    float4 pre[8];
#pragma unroll
    for (int j = 0; j < 4; ++j) { pre[j] = S0[so[j]]; pre[4 + j] = S1[so[j]]; }
#pragma unroll 1
    for (int kc = 0; kc < 8; ++kc) {
        float4* d = wb4 + (kc & 1) * 2560;
#pragma unroll
        for (int j = 0; j < 4; ++j) { d[dofs[j]] = pre[j]; d[1280 + dofs[j]] = pre[4 + j]; }
        if (kc < 7) {
#pragma unroll
            for (int j = 0; j < 4; ++j) {
                pre[j] = S0[so[j] + (kc + 1) * 4]; pre[4 + j] = S1[so[j] + (kc + 1) * 4];
            }
        }
        __syncthreads();
        u32 wtb = wbu + (kc & 1) * 40960;
#pragma unroll
        for (int k16 = 0; k16 < 2; ++k16) {
            u32 kA = (u32)((kc * 32 + k16 * 16) * 2);
            u32 ah[8], al[8], bh[8], bl[8];
            LDSM4(ah[0], ah[1], ah[2], ah[3], aHi + aoff + kA);
            LDSM4(ah[4], ah[5], ah[6], ah[7], aHi + aoff + 8448 + kA);   // m0=16: 16*SA*2
            LDSM4(al[0], al[1], al[2], al[3], aLo + aoff + kA);
            LDSM4(al[4], al[5], al[6], al[7], aLo + aoff + 8448 + kA);
            u32 b0a = wtb + boff + (u32)(w * 2560) + (u32)(k16 * 32);    // w*32 rows * 80B
            LDSM4(bh[0], bh[1], bh[2], bh[3], b0a);
            LDSM4(bh[4], bh[5], bh[6], bh[7], b0a + 1280);               // +16 rows
            LDSM4(bl[0], bl[1], bl[2], bl[3], b0a + 20480);              // lo tile
            LDSM4(bl[4], bl[5], bl[6], bl[7], b0a + 20480 + 1280);
#pragma unroll
            for (int mt = 0; mt < 2; ++mt)
#pragma unroll
                for (int nt = 0; nt < 4; ++nt) {
                    float* cc = c[mt][nt];
                    MMA(cc, &ah[mt * 4], bh[nt * 2], bh[nt * 2 + 1]);
                    MMA(cc, &al[mt * 4], bh[nt * 2], bh[nt * 2 + 1]);
                    MMA(cc, &ah[mt * 4], bl[nt * 2], bl[nt * 2 + 1]);
                }
        }
    }
}

// store tanh'd fragments as bf16 hi/lo into a state array
__device__ __forceinline__ void frag_store(float (&c)[2][4][4],
    __nv_bfloat16* shi, __nv_bfloat16* slo, int lane, int w)
{
#pragma unroll
    for (int mt = 0; mt < 2; ++mt)
#pragma unroll
        for (int nt = 0; nt < 4; ++nt)
#pragma unroll
            for (int hv = 0; hv < 2; ++hv) {
                int row = mt * 16 + (lane >> 2) + hv * 8;
                int col = w * 32 + nt * 8 + (lane & 3) * 2;
                float v0 = tanh_e(c[mt][nt][hv * 2]);
                float v1 = tanh_e(c[mt][nt][hv * 2 + 1]);
                __nv_bfloat162 ph = __floats2bfloat162_rn(v0, v1);
                float q0 = v0 - __bfloat162float(__low2bfloat16(ph));
                float q1 = v1 - __bfloat162float(__high2bfloat16(ph));
                __nv_bfloat162 pl = __floats2bfloat162_rn(q0, q1);
                *(__nv_bfloat162*)(shi + row * SA + col) = ph;
                *(__nv_bfloat162*)(slo + row * SA + col) = pl;
            }
}

__global__ __launch_bounds__(NTH, 1)
void rnn_mma_kernel(const int* __restrict__ inputs, const float* __restrict__ b2,
                    float* __restrict__ out)
{
    extern __shared__ char smraw[];
    __nv_bfloat16* h1hi = (__nv_bfloat16*)smraw;                 // 32*264*2 = 16896 B
    __nv_bfloat16* h1lo = h1hi + 32 * SA;
    __nv_bfloat16* h2hi = h1lo + 32 * SA;
    __nv_bfloat16* h2lo = h2hi + 32 * SA;
    float4* wb4 = (float4*)(smraw + 67584);                      // 81920 B (2 buf x hi/lo)
    float*  b2s = (float*)(smraw + 149504);                      // 1024 B
    int*    toks = (int*)(smraw + 150528);                       // 10240 B

    const int tid = threadIdx.x, lane = tid & 31, w = tid >> 5;
    const int bb = blockIdx.x * M2;
    const u32 smb = smem_u32(smraw);
    const u32 aH1h = smb, aH1l = smb + 16896, aH2h = smb + 33792, aH2l = smb + 50688;
    const u32 wbu = smb + 67584;

    for (int i = tid; i < 4 * 32 * SA / 2; i += NTH) ((u32*)h1hi)[i] = 0;
    for (int i = tid; i < H / 4; i += NTH) ((float4*)b2s)[i] = ((const float4*)b2)[i];
    for (int i = tid; i < M2 * T; i += NTH)
        toks[i] = inputs[(bb + i / T) * T + (i % T)];
    __syncthreads();

#pragma unroll 1
    for (int t = 0; t < T; ++t) {
        // ---- layer 1: C = embW[tok] ; C += h1_old @ U1^T ----
        float c[2][4][4];
#pragma unroll
        for (int mt = 0; mt < 2; ++mt)
#pragma unroll
            for (int hv = 0; hv < 2; ++hv) {
                int row = mt * 16 + (lane >> 2) + hv * 8;
                const float* er = g_embW + (size_t)toks[row * T + t] * H;
#pragma unroll
                for (int nt = 0; nt < 4; ++nt) {
                    float2 x = *(const float2*)(er + w * 32 + nt * 8 + (lane & 3) * 2);
                    c[mt][nt][hv * 2] = x.x; c[mt][nt][hv * 2 + 1] = x.y;
                }
            }
        gemm_mma(g_wbf[0][0], g_wbf[0][1], aH1h, aH1l, wb4, wbu, c, tid, lane, w);
        __syncthreads();                    // all warps done reading h1 / wbuf
        frag_store(c, h1hi, h1lo, lane, w); // h1 = tanh(...)
        __syncthreads();                    // new h1 visible

        // ---- layer 2: C = b2 ; C += h1_new @ W2^T + h2_old @ U2^T ----
        float c2[2][4][4];
#pragma unroll
        for (int nt = 0; nt < 4; ++nt) {
            float2 bv = *(const float2*)(b2s + w * 32 + nt * 8 + (lane & 3) * 2);
#pragma unroll
            for (int mt = 0; mt < 2; ++mt) {
                c2[mt][nt][0] = bv.x; c2[mt][nt][1] = bv.y;
                c2[mt][nt][2] = bv.x; c2[mt][nt][3] = bv.y;
            }
        }
        gemm_mma(g_wbf[1][0], g_wbf[1][1], aH1h, aH1l, wb4, wbu, c2, tid, lane, w);
        gemm_mma(g_wbf[2][0], g_wbf[2][1], aH2h, aH2l, wb4, wbu, c2, tid, lane, w);
        __syncthreads();                    // all warps done reading h2 / wbuf

        if (t == T - 1) {
#pragma unroll
            for (int mt = 0; mt < 2; ++mt)
#pragma unroll
                for (int nt = 0; nt < 4; ++nt)
#pragma unroll
                    for (int hv = 0; hv < 2; ++hv) {
                        int row = mt * 16 + (lane >> 2) + hv * 8;
                        int col = w * 32 + nt * 8 + (lane & 3) * 2;
                        float v0 = tanh_e(c2[mt][nt][hv * 2]);
                        float v1 = tanh_e(c2[mt][nt][hv * 2 + 1]);
                        float2 o;
                        o.x = __fdividef(1.f, 1.f + __expf(-v0));
                        o.y = __fdividef(1.f, 1.f + __expf(-v1));
                        *(float2*)&out[(size_t)(bb + row) * H + col] = o;
                    }
        } else {
            frag_store(c2, h2hi, h2lo, lane, w);
            // publish of new h2 is covered by next step's chunk syncs before any h2 read
        }
    }
}

extern "C" void kernel_launch(void* const* d_in, const int* in_sizes, int n_in,
                              void* d_out, int out_size)
{
    const int*   inputs = (const int*)  d_in[0];
    const float* emb    = (const float*)d_in[1];
    const float* W1     = (const float*)d_in[2];
    const float* U1     = (const float*)d_in[3];
    const float* b1     = (const float*)d_in[4];
    const float* W2     = (const float*)d_in[5];
    const float* U2     = (const float*)d_in[6];
    const float* b2     = (const float*)d_in[7];
    float* out = (float*)d_out;

    const int smem_embw = (EMB * H + EMB * HS) * (int)sizeof(float);  // 116800
    const int smem_main = 160768;

    cudaFuncSetAttribute(embw_kernel,    cudaFuncAttributeMaxDynamicSharedMemorySize, smem_embw);
    cudaFuncSetAttribute(rnn_mma_kernel, cudaFuncAttributeMaxDynamicSharedMemorySize, smem_main);

    prep_weights<<<(3 * H * H + 255) / 256, 256>>>(U1, W2, U2);
    embw_kernel<<<(VOCAB + 31) / 32, NTH, smem_embw>>>(emb, W1, b1);
    rnn_mma_kernel<<<BATCH / M2, NTH, smem_main>>>(inputs, b2, out);
}

// round 15
// speedup vs baseline: 2.0104x; 1.2727x over previous
#include <cuda_runtime.h>
#include <cuda_bf16.h>
#include <cstdint>
#include <math.h>

#define BATCH 4096
#define T     80
#define VOCAB 10000
#define EMB   100
#define H     256
#define HS    36
#define M2    32
#define NTH   256
#define SA    264          // state k-stride (bf16): odd 16B-phase -> conflict-free ldmatrix

typedef uint32_t u32; typedef unsigned long long u64;

__device__ float g_embW[(size_t)VOCAB * H];
// B fragments in lane order: [gemm][term(hi/lo)][nblock(8)][k16(16)][pair(2)] x [lane(32)][4xu32]
__device__ __align__(16) u32 g_wB[3 * 2 * 8 * 16 * 2 * 128];

__device__ __forceinline__ u32 smem_u32(const void* p) {
    u32 a; asm("{ .reg .u64 t; cvta.to.shared.u64 t, %1; cvt.u32.u64 %0, t; }" : "=r"(a) : "l"(p));
    return a;
}
__device__ __forceinline__ float tanh_e(float x) {
    float e = __expf(-2.f * fabsf(x));
    return copysignf(__fdividef(1.f - e, 1.f + e), x);
}
__device__ __forceinline__ u64 ffma2(u64 a, u64 b, u64 c) {
    u64 d; asm("fma.rn.f32x2 %0, %1, %2, %3;" : "=l"(d) : "l"(a), "l"(b), "l"(c)); return d;
}
__device__ __forceinline__ u64 splat2(float x) { u64 d; asm("mov.b64 %0, {%1, %1};" : "=l"(d) : "f"(x)); return d; }
__device__ __forceinline__ u64 pack2(float lo, float hi) { u64 d; asm("mov.b64 %0, {%1, %2};" : "=l"(d) : "f"(lo), "f"(hi)); return d; }
__device__ __forceinline__ void unpack2(u64 p, float& lo, float& hi) { asm("mov.b64 {%0, %1}, %2;" : "=f"(lo), "=f"(hi) : "l"(p)); }

#define LDSM4(r0, r1, r2, r3, a) \
    asm volatile("ldmatrix.sync.aligned.m8n8.x4.shared.b16 {%0,%1,%2,%3}, [%4];" \
                 : "=r"(r0), "=r"(r1), "=r"(r2), "=r"(r3) : "r"(a))
#define MMA(c, a, b0, b1) \
    asm volatile("mma.sync.aligned.m16n8k16.row.col.f32.bf16.bf16.f32 " \
                 "{%0,%1,%2,%3}, {%4,%5,%6,%7}, {%8,%9}, {%0,%1,%2,%3};" \
                 : "+f"((c)[0]), "+f"((c)[1]), "+f"((c)[2]), "+f"((c)[3]) \
                 : "r"((a)[0]), "r"((a)[1]), "r"((a)[2]), "r"((a)[3]), "r"(b0), "r"(b1))

// ---- prep: weights -> bf16 hi/lo B-fragments in lane order ----
// Fragment mapping (same as the proven ldmatrix path): for entry (g,term,nb,k16,pr),
// lane l, u32 j: nt = pr*2 + (j>>1), reg = j&1;
//   n = nb*32 + nt*8 + (l>>2);  k = k16*16 + reg*8 + (l&3)*2;
//   u32 = bf16x2{ W[k][n] (low), W[k+1][n] (high) }
__global__ void prep_weights(const float* __restrict__ U1, const float* __restrict__ W2,
                             const float* __restrict__ U2)
{
    int idx = blockIdx.x * blockDim.x + threadIdx.x;   // one 16B entry per thread
    if (idx >= 3 * 2 * 8 * 16 * 2 * 32) return;
    int lane = idx & 31, pr = (idx >> 5) & 1, k16 = (idx >> 6) & 15;
    int nb = (idx >> 10) & 7, term = (idx >> 13) & 1, g = idx >> 14;
    const float* s = g == 0 ? U1 : g == 1 ? W2 : U2;
    u32 o[4];
#pragma unroll
    for (int j = 0; j < 4; ++j) {
        int nt = pr * 2 + (j >> 1), reg = j & 1;
        int n = nb * 32 + nt * 8 + (lane >> 2);
        int k = k16 * 16 + reg * 8 + (lane & 3) * 2;
        float v0 = s[k * H + n], v1 = s[(k + 1) * H + n];
        __nv_bfloat162 ph = __floats2bfloat162_rn(v0, v1);
        if (term == 1) {
            float r0 = v0 - __bfloat162float(__low2bfloat16(ph));
            float r1 = v1 - __bfloat162float(__high2bfloat16(ph));
            ph = __floats2bfloat162_rn(r0, r1);
        }
        o[j] = *(u32*)&ph;
    }
    ((uint4*)g_wB)[idx] = make_uint4(o[0], o[1], o[2], o[3]);
}

// ---- embW = b1 + emb @ W1 (R10-proven, fp32) ----
__global__ __launch_bounds__(NTH, 1)
void embw_kernel(const float* __restrict__ emb, const float* __restrict__ W1,
                 const float* __restrict__ b1)
{
    extern __shared__ float sm[];
    float* W1s = sm; float* xs = W1s + EMB * H;
    const int tid = threadIdx.x, ty = tid >> 6, tx = tid & 63;
    const int r0 = ty * 8, c0 = tx * 4, v0 = blockIdx.x * 32;
#pragma unroll
    for (int j = 0; j < (EMB * H / 4) / NTH; ++j)
        ((float4*)W1s)[tid + j * NTH] = ((const float4*)W1)[tid + j * NTH];
    for (int i = tid; i < EMB * HS; i += NTH) xs[i] = 0.f;
    __syncthreads();
    for (int i = tid; i < 32 * (EMB / 4); i += NTH) {
        int r = i / (EMB / 4), q = i % (EMB / 4), v = v0 + r;
        if (v < VOCAB) {
            float4 x = ((const float4*)emb)[v * (EMB / 4) + q];
            xs[(4 * q + 0) * HS + r] = x.x; xs[(4 * q + 1) * HS + r] = x.y;
            xs[(4 * q + 2) * HS + r] = x.z; xs[(4 * q + 3) * HS + r] = x.w;
        }
    }
    const float4 b1v = ((const float4*)b1)[tx];
    __syncthreads();
    u64 acc[4][4];
    const u64 bp[4] = { splat2(b1v.x), splat2(b1v.y), splat2(b1v.z), splat2(b1v.w) };
#pragma unroll
    for (int p = 0; p < 4; ++p)
#pragma unroll
        for (int j = 0; j < 4; ++j) acc[p][j] = bp[j];
#pragma unroll 4
    for (int k = 0; k < EMB; ++k) {
        float4 a0 = *(const float4*)&xs[k * HS + r0];
        float4 a1 = *(const float4*)&xs[k * HS + r0 + 4];
        float4 b  = *(const float4*)&W1s[k * H + c0];
        u64 ap[4] = { pack2(a0.x, a0.y), pack2(a0.z, a0.w), pack2(a1.x, a1.y), pack2(a1.z, a1.w) };
        u64 bb[4] = { splat2(b.x), splat2(b.y), splat2(b.z), splat2(b.w) };
#pragma unroll
        for (int p = 0; p < 4; ++p)
#pragma unroll
            for (int j = 0; j < 4; ++j) acc[p][j] = ffma2(ap[p], bb[j], acc[p][j]);
    }
#pragma unroll
    for (int i = 0; i < 8; ++i) {
        int v = v0 + r0 + i;
        if (v < VOCAB) {
            float o[4];
#pragma unroll
            for (int j = 0; j < 4; ++j) { float lo, hi; unpack2(acc[i >> 1][j], lo, hi); o[j] = (i & 1) ? hi : lo; }
            *(float4*)&g_embW[(size_t)v * H + c0] = make_float4(o[0], o[1], o[2], o[3]);
        }
    }
}

// load one k16's B fragments (8 u32) for (gemm g, term, warp nb) via 2x LDG.128
__device__ __forceinline__ void ldB(int g, int term, int nb, int t, int lane, u32 b[8]) {
    const uint4* P = (const uint4*)g_wB;
    int e = ((((g * 2 + term) * 8 + nb) * 16 + t) * 2) * 32 + lane;
    uint4 v0 = __ldg(&P[e]);
    uint4 v1 = __ldg(&P[e + 32]);
    b[0] = v0.x; b[1] = v0.y; b[2] = v0.z; b[3] = v0.w;
    b[4] = v1.x; b[5] = v1.y; b[6] = v1.z; b[7] = v1.w;
}

// C += state(A via ldmatrix, bf16 hi/lo) @ W^T (B via direct LDG fragments)
// 16 k16 iterations, distance-1 register prefetch of B, NO syncs inside.
__device__ __forceinline__ void gemm_f(int g, u32 aHi, u32 aLo,
    float (&c)[2][4][4], int lane, int w, u32 aoff)
{
    u32 bhC[8], blC[8], bhN[8], blN[8];
    ldB(g, 0, w, 0, lane, bhC);
    ldB(g, 1, w, 0, lane, blC);
#pragma unroll
    for (int t = 0; t < 16; ++t) {
        if (t < 15) { ldB(g, 0, w, t + 1, lane, bhN); ldB(g, 1, w, t + 1, lane, blN); }
        u32 kA = (u32)(t * 32);                    // 16 k * 2B
        u32 ah[8], al[8];
        LDSM4(ah[0], ah[1], ah[2], ah[3], aHi + aoff + kA);
        LDSM4(ah[4], ah[5], ah[6], ah[7], aHi + aoff + 8448 + kA);   // +16 rows (16*SA*2)
        LDSM4(al[0], al[1], al[2], al[3], aLo + aoff + kA);
        LDSM4(al[4], al[5], al[6], al[7], aLo + aoff + 8448 + kA);
#pragma unroll
        for (int mt = 0; mt < 2; ++mt)
#pragma unroll
            for (int nt = 0; nt < 4; ++nt) {
                float* cc = c[mt][nt];
                MMA(cc, &ah[mt * 4], bhC[nt * 2], bhC[nt * 2 + 1]);
                MMA(cc, &al[mt * 4], bhC[nt * 2], bhC[nt * 2 + 1]);
                MMA(cc, &ah[mt * 4], blC[nt * 2], blC[nt * 2 + 1]);
            }
        if (t < 15) {
#pragma unroll
            for (int q = 0; q < 8; ++q) { bhC[q] = bhN[q]; blC[q] = blN[q]; }
        }
    }
}

// store tanh'd fragments as bf16 hi/lo into a state array
__device__ __forceinline__ void frag_store(float (&c)[2][4][4],
    __nv_bfloat16* shi, __nv_bfloat16* slo, int lane, int w)
{
#pragma unroll
    for (int mt = 0; mt < 2; ++mt)
#pragma unroll
        for (int nt = 0; nt < 4; ++nt)
#pragma unroll
            for (int hv = 0; hv < 2; ++hv) {
                int row = mt * 16 + (lane >> 2) + hv * 8;
                int col = w * 32 + nt * 8 + (lane & 3) * 2;
                float v0 = tanh_e(c[mt][nt][hv * 2]);
                float v1 = tanh_e(c[mt][nt][hv * 2 + 1]);
                __nv_bfloat162 ph = __floats2bfloat162_rn(v0, v1);
                float q0 = v0 - __bfloat162float(__low2bfloat16(ph));
                float q1 = v1 - __bfloat162float(__high2bfloat16(ph));
                __nv_bfloat162 pl = __floats2bfloat162_rn(q0, q1);
                *(__nv_bfloat162*)(shi + row * SA + col) = ph;
                *(__nv_bfloat162*)(slo + row * SA + col) = pl;
            }
}

__global__ __launch_bounds__(NTH, 1)
void rnn_mma_kernel(const int* __restrict__ inputs, const float* __restrict__ b2,
                    float* __restrict__ out)
{
    extern __shared__ char smraw[];
    __nv_bfloat16* h1hi = (__nv_bfloat16*)smraw;          // 32*264*2 = 16896 B each
    __nv_bfloat16* h1lo = h1hi + 32 * SA;
    __nv_bfloat16* h2hi = h1lo + 32 * SA;
    __nv_bfloat16* h2lo = h2hi + 32 * SA;
    float* b2s  = (float*)(smraw + 67584);                // 1024 B
    int*   toks = (int*)(smraw + 68608);                  // 10240 B

    const int tid = threadIdx.x, lane = tid & 31, w = tid >> 5;
    const int bb = blockIdx.x * M2;
    const u32 smb = smem_u32(smraw);
    const u32 aH1h = smb, aH1l = smb + 16896, aH2h = smb + 33792, aH2l = smb + 50688;

    const int grp = lane >> 3, lr = lane & 7;
    const u32 aoff = (u32)(((lr + (grp & 1) * 8) * SA + (grp >> 1) * 8) * 2);

    for (int i = tid; i < 4 * 32 * SA / 2; i += NTH) ((u32*)h1hi)[i] = 0;
    for (int i = tid; i < H / 4; i += NTH) ((float4*)b2s)[i] = ((const float4*)b2)[i];
    for (int i = tid; i < M2 * T; i += NTH)
        toks[i] = inputs[(bb + i / T) * T + (i % T)];
    __syncthreads();

#pragma unroll 1
    for (int t = 0; t < T; ++t) {
        // ---- layer 1: C = embW[tok] ; C += h1_old @ U1^T ----
        float c[2][4][4];
#pragma unroll
        for (int mt = 0; mt < 2; ++mt)
#pragma unroll
            for (int hv = 0; hv < 2; ++hv) {
                int row = mt * 16 + (lane >> 2) + hv * 8;
                const float* er = g_embW + (size_t)toks[row * T + t] * H;
#pragma unroll
                for (int nt = 0; nt < 4; ++nt) {
                    float2 x = *(const float2*)(er + w * 32 + nt * 8 + (lane & 3) * 2);
                    c[mt][nt][hv * 2] = x.x; c[mt][nt][hv * 2 + 1] = x.y;
                }
            }
        gemm_f(0, aH1h, aH1l, c, lane, w, aoff);
        __syncthreads();                    // all warps done reading h1
        frag_store(c, h1hi, h1lo, lane, w); // h1 = tanh(...)
        __syncthreads();                    // new h1 visible

        // ---- layer 2: C = b2 ; C += h1_new @ W2^T + h2_old @ U2^T ----
        float c2[2][4][4];
#pragma unroll
        for (int nt = 0; nt < 4; ++nt) {
            float2 bv = *(const float2*)(b2s + w * 32 + nt * 8 + (lane & 3) * 2);
#pragma unroll
            for (int mt = 0; mt < 2; ++mt) {
                c2[mt][nt][0] = bv.x; c2[mt][nt][1] = bv.y;
                c2[mt][nt][2] = bv.x; c2[mt][nt][3] = bv.y;
            }
        }
        gemm_f(1, aH1h, aH1l, c2, lane, w, aoff);
        gemm_f(2, aH2h, aH2l, c2, lane, w, aoff);
        __syncthreads();                    // all warps done reading h2

        if (t == T - 1) {
#pragma unroll
            for (int mt = 0; mt < 2; ++mt)
#pragma unroll
                for (int nt = 0; nt < 4; ++nt)
#pragma unroll
                    for (int hv = 0; hv < 2; ++hv) {
                        int row = mt * 16 + (lane >> 2) + hv * 8;
                        int col = w * 32 + nt * 8 + (lane & 3) * 2;
                        float v0 = tanh_e(c2[mt][nt][hv * 2]);
                        float v1 = tanh_e(c2[mt][nt][hv * 2 + 1]);
                        float2 o;
                        o.x = __fdividef(1.f, 1.f + __expf(-v0));
                        o.y = __fdividef(1.f, 1.f + __expf(-v1));
                        *(float2*)&out[(size_t)(bb + row) * H + col] = o;
                    }
        } else {
            frag_store(c2, h2hi, h2lo, lane, w);
            __syncthreads();                // new h2 visible before next step's gemms
        }
    }
}

extern "C" void kernel_launch(void* const* d_in, const int* in_sizes, int n_in,
                              void* d_out, int out_size)
{
    const int*   inputs = (const int*)  d_in[0];
    const float* emb    = (const float*)d_in[1];
    const float* W1     = (const float*)d_in[2];
    const float* U1     = (const float*)d_in[3];
    const float* b1     = (const float*)d_in[4];
    const float* W2     = (const float*)d_in[5];
    const float* U2     = (const float*)d_in[6];
    const float* b2     = (const float*)d_in[7];
    float* out = (float*)d_out;

    const int smem_embw = (EMB * H + EMB * HS) * (int)sizeof(float);  // 116800
    const int smem_main = 78848;

    cudaFuncSetAttribute(embw_kernel,    cudaFuncAttributeMaxDynamicSharedMemorySize, smem_embw);
    cudaFuncSetAttribute(rnn_mma_kernel, cudaFuncAttributeMaxDynamicSharedMemorySize, smem_main);

    prep_weights<<<(3 * 2 * 8 * 16 * 2 * 32 + 255) / 256, 256>>>(U1, W2, U2);
    embw_kernel<<<(VOCAB + 31) / 32, NTH, smem_embw>>>(emb, W1, b1);
    rnn_mma_kernel<<<BATCH / M2, NTH, smem_main>>>(inputs, b2, out);
}

// round 16
// speedup vs baseline: 3.1262x; 1.5550x over previous
#include <cuda_runtime.h>
#include <cuda_bf16.h>
#include <cstdint>
#include <math.h>

#define BATCH 4096
#define T     80
#define VOCAB 10000
#define EMB   100
#define H     256
#define HS    36
#define M2    32
#define NTH   256
#define SA    264          // state k-stride (bf16): odd 16B-phase -> conflict-free ldmatrix

typedef uint32_t u32; typedef unsigned long long u64;

__device__ float g_embW[(size_t)VOCAB * H];
// B fragments in lane order: [gemm][term(hi/lo)][nblock(8)][k16(16)][pair(2)] x [lane(32)][4xu32]
__device__ __align__(16) u32 g_wB[3 * 2 * 8 * 16 * 2 * 128];

__device__ __forceinline__ u32 smem_u32(const void* p) {
    u32 a; asm("{ .reg .u64 t; cvta.to.shared.u64 t, %1; cvt.u32.u64 %0, t; }" : "=r"(a) : "l"(p));
    return a;
}
__device__ __forceinline__ float tanh_e(float x) {
    float e = __expf(-2.f * fabsf(x));
    return copysignf(__fdividef(1.f - e, 1.f + e), x);
}
__device__ __forceinline__ u64 ffma2(u64 a, u64 b, u64 c) {
    u64 d; asm("fma.rn.f32x2 %0, %1, %2, %3;" : "=l"(d) : "l"(a), "l"(b), "l"(c)); return d;
}
__device__ __forceinline__ u64 splat2(float x) { u64 d; asm("mov.b64 %0, {%1, %1};" : "=l"(d) : "f"(x)); return d; }
__device__ __forceinline__ u64 pack2(float lo, float hi) { u64 d; asm("mov.b64 %0, {%1, %2};" : "=l"(d) : "f"(lo), "f"(hi)); return d; }
__device__ __forceinline__ void unpack2(u64 p, float& lo, float& hi) { asm("mov.b64 {%0, %1}, %2;" : "=f"(lo), "=f"(hi) : "l"(p)); }

#define LDSM4(r0, r1, r2, r3, a) \
    asm volatile("ldmatrix.sync.aligned.m8n8.x4.shared.b16 {%0,%1,%2,%3}, [%4];" \
                 : "=r"(r0), "=r"(r1), "=r"(r2), "=r"(r3) : "r"(a))
#define MMA(c, a, b0, b1) \
    asm volatile("mma.sync.aligned.m16n8k16.row.col.f32.bf16.bf16.f32 " \
                 "{%0,%1,%2,%3}, {%4,%5,%6,%7}, {%8,%9}, {%0,%1,%2,%3};" \
                 : "+f"((c)[0]), "+f"((c)[1]), "+f"((c)[2]), "+f"((c)[3]) \
                 : "r"((a)[0]), "r"((a)[1]), "r"((a)[2]), "r"((a)[3]), "r"(b0), "r"(b1))

// ---- prep: weights -> bf16 hi/lo B-fragments in lane order (R15-proven) ----
__global__ void prep_weights(const float* __restrict__ U1, const float* __restrict__ W2,
                             const float* __restrict__ U2)
{
    int idx = blockIdx.x * blockDim.x + threadIdx.x;
    if (idx >= 3 * 2 * 8 * 16 * 2 * 32) return;
    int lane = idx & 31, pr = (idx >> 5) & 1, k16 = (idx >> 6) & 15;
    int nb = (idx >> 10) & 7, term = (idx >> 13) & 1, g = idx >> 14;
    const float* s = g == 0 ? U1 : g == 1 ? W2 : U2;
    u32 o[4];
#pragma unroll
    for (int j = 0; j < 4; ++j) {
        int nt = pr * 2 + (j >> 1), reg = j & 1;
        int n = nb * 32 + nt * 8 + (lane >> 2);
        int k = k16 * 16 + reg * 8 + (lane & 3) * 2;
        float v0 = s[k * H + n], v1 = s[(k + 1) * H + n];
        __nv_bfloat162 ph = __floats2bfloat162_rn(v0, v1);
        if (term == 1) {
            float r0 = v0 - __bfloat162float(__low2bfloat16(ph));
            float r1 = v1 - __bfloat162float(__high2bfloat16(ph));
            ph = __floats2bfloat162_rn(r0, r1);
        }
        o[j] = *(u32*)&ph;
    }
    ((uint4*)g_wB)[idx] = make_uint4(o[0], o[1], o[2], o[3]);
}

// ---- embW = b1 + emb @ W1 (R10-proven, fp32) ----
__global__ __launch_bounds__(NTH, 1)
void embw_kernel(const float* __restrict__ emb, const float* __restrict__ W1,
                 const float* __restrict__ b1)
{
    extern __shared__ float sm[];
    float* W1s = sm; float* xs = W1s + EMB * H;
    const int tid = threadIdx.x, ty = tid >> 6, tx = tid & 63;
    const int r0 = ty * 8, c0 = tx * 4, v0 = blockIdx.x * 32;
#pragma unroll
    for (int j = 0; j < (EMB * H / 4) / NTH; ++j)
        ((float4*)W1s)[tid + j * NTH] = ((const float4*)W1)[tid + j * NTH];
    for (int i = tid; i < EMB * HS; i += NTH) xs[i] = 0.f;
    __syncthreads();
    for (int i = tid; i < 32 * (EMB / 4); i += NTH) {
        int r = i / (EMB / 4), q = i % (EMB / 4), v = v0 + r;
        if (v < VOCAB) {
            float4 x = ((const float4*)emb)[v * (EMB / 4) + q];
            xs[(4 * q + 0) * HS + r] = x.x; xs[(4 * q + 1) * HS + r] = x.y;
            xs[(4 * q + 2) * HS + r] = x.z; xs[(4 * q + 3) * HS + r] = x.w;
        }
    }
    const float4 b1v = ((const float4*)b1)[tx];
    __syncthreads();
    u64 acc[4][4];
    const u64 bp[4] = { splat2(b1v.x), splat2(b1v.y), splat2(b1v.z), splat2(b1v.w) };
#pragma unroll
    for (int p = 0; p < 4; ++p)
#pragma unroll
        for (int j = 0; j < 4; ++j) acc[p][j] = bp[j];
#pragma unroll 4
    for (int k = 0; k < EMB; ++k) {
        float4 a0 = *(const float4*)&xs[k * HS + r0];
        float4 a1 = *(const float4*)&xs[k * HS + r0 + 4];
        float4 b  = *(const float4*)&W1s[k * H + c0];
        u64 ap[4] = { pack2(a0.x, a0.y), pack2(a0.z, a0.w), pack2(a1.x, a1.y), pack2(a1.z, a1.w) };
        u64 bb[4] = { splat2(b.x), splat2(b.y), splat2(b.z), splat2(b.w) };
#pragma unroll
        for (int p = 0; p < 4; ++p)
#pragma unroll
            for (int j = 0; j < 4; ++j) acc[p][j] = ffma2(ap[p], bb[j], acc[p][j]);
    }
#pragma unroll
    for (int i = 0; i < 8; ++i) {
        int v = v0 + r0 + i;
        if (v < VOCAB) {
            float o[4];
#pragma unroll
            for (int j = 0; j < 4; ++j) { float lo, hi; unpack2(acc[i >> 1][j], lo, hi); o[j] = (i & 1) ? hi : lo; }
            *(float4*)&g_embW[(size_t)v * H + c0] = make_float4(o[0], o[1], o[2], o[3]);
        }
    }
}

// load one k16's B fragments (8 u32) for (gemm g, term, warp nb)
__device__ __forceinline__ void ldB(int g, int term, int nb, int t, int lane, u32 b[8]) {
    const uint4* P = (const uint4*)g_wB;
    int e = ((((g * 2 + term) * 8 + nb) * 16 + t) * 2) * 32 + lane;
    uint4 v0 = __ldg(&P[e]);
    uint4 v1 = __ldg(&P[e + 32]);
    b[0] = v0.x; b[1] = v0.y; b[2] = v0.z; b[3] = v0.w;
    b[4] = v1.x; b[5] = v1.y; b[6] = v1.z; b[7] = v1.w;
}

__device__ __forceinline__ void mma_block(float (&c)[2][4][4],
    const u32 ah[8], const u32 al[8], const u32 bh[8], const u32 bl[8])
{
#pragma unroll
    for (int mt = 0; mt < 2; ++mt)
#pragma unroll
        for (int nt = 0; nt < 4; ++nt) {
            float* cc = c[mt][nt];
            MMA(cc, &ah[mt * 4], bh[nt * 2], bh[nt * 2 + 1]);
            MMA(cc, &al[mt * 4], bh[nt * 2], bh[nt * 2 + 1]);
            MMA(cc, &ah[mt * 4], bl[nt * 2], bl[nt * 2 + 1]);
        }
}

// layer-1 GEMM: distance-2 B prefetch (two buffers in flight)
__device__ __forceinline__ void gemm_l1(u32 aHi, u32 aLo,
    float (&c)[2][4][4], int lane, int w, u32 aoff)
{
    u32 bh[2][8], bl[2][8];
    ldB(0, 0, w, 0, lane, bh[0]); ldB(0, 1, w, 0, lane, bl[0]);
    ldB(0, 0, w, 1, lane, bh[1]); ldB(0, 1, w, 1, lane, bl[1]);
#pragma unroll
    for (int t = 0; t < 16; ++t) {
        u32 kA = (u32)(t * 32);
        u32 ah[8], al[8];
        LDSM4(ah[0], ah[1], ah[2], ah[3], aHi + aoff + kA);
        LDSM4(ah[4], ah[5], ah[6], ah[7], aHi + aoff + 8448 + kA);
        LDSM4(al[0], al[1], al[2], al[3], aLo + aoff + kA);
        LDSM4(al[4], al[5], al[6], al[7], aLo + aoff + 8448 + kA);
        mma_block(c, ah, al, bh[t & 1], bl[t & 1]);
        if (t + 2 < 16) {       // refill the buffer just consumed (register-renamed)
            ldB(0, 0, w, t + 2, lane, bh[t & 1]);
            ldB(0, 1, w, t + 2, lane, bl[t & 1]);
        }
    }
}

// layer-2 fused GEMM: C += h1@W2^T + h2@U2^T, one k-loop, distance-1 prefetch of both
__device__ __forceinline__ void gemm_l2(u32 a1Hi, u32 a1Lo, u32 a2Hi, u32 a2Lo,
    float (&c)[2][4][4], int lane, int w, u32 aoff)
{
    u32 b1h[8], b1l[8], b2h[8], b2l[8], n1h[8], n1l[8], n2h[8], n2l[8];
    ldB(1, 0, w, 0, lane, b1h); ldB(1, 1, w, 0, lane, b1l);
    ldB(2, 0, w, 0, lane, b2h); ldB(2, 1, w, 0, lane, b2l);
#pragma unroll
    for (int t = 0; t < 16; ++t) {
        if (t < 15) {
            ldB(1, 0, w, t + 1, lane, n1h); ldB(1, 1, w, t + 1, lane, n1l);
            ldB(2, 0, w, t + 1, lane, n2h); ldB(2, 1, w, t + 1, lane, n2l);
        }
        u32 kA = (u32)(t * 32);
        u32 ah[8], al[8];
        LDSM4(ah[0], ah[1], ah[2], ah[3], a1Hi + aoff + kA);
        LDSM4(ah[4], ah[5], ah[6], ah[7], a1Hi + aoff + 8448 + kA);
        LDSM4(al[0], al[1], al[2], al[3], a1Lo + aoff + kA);
        LDSM4(al[4], al[5], al[6], al[7], a1Lo + aoff + 8448 + kA);
        mma_block(c, ah, al, b1h, b1l);
        LDSM4(ah[0], ah[1], ah[2], ah[3], a2Hi + aoff + kA);
        LDSM4(ah[4], ah[5], ah[6], ah[7], a2Hi + aoff + 8448 + kA);
        LDSM4(al[0], al[1], al[2], al[3], a2Lo + aoff + kA);
        LDSM4(al[4], al[5], al[6], al[7], a2Lo + aoff + 8448 + kA);
        mma_block(c, ah, al, b2h, b2l);
        if (t < 15) {
#pragma unroll
            for (int q = 0; q < 8; ++q) {
                b1h[q] = n1h[q]; b1l[q] = n1l[q];
                b2h[q] = n2h[q]; b2l[q] = n2l[q];
            }
        }
    }
}

// store tanh'd fragments as bf16 hi/lo into a state array
__device__ __forceinline__ void frag_store(float (&c)[2][4][4],
    __nv_bfloat16* shi, __nv_bfloat16* slo, int lane, int w)
{
#pragma unroll
    for (int mt = 0; mt < 2; ++mt)
#pragma unroll
        for (int nt = 0; nt < 4; ++nt)
#pragma unroll
            for (int hv = 0; hv < 2; ++hv) {
                int row = mt * 16 + (lane >> 2) + hv * 8;
                int col = w * 32 + nt * 8 + (lane & 3) * 2;
                float v0 = tanh_e(c[mt][nt][hv * 2]);
                float v1 = tanh_e(c[mt][nt][hv * 2 + 1]);
                __nv_bfloat162 ph = __floats2bfloat162_rn(v0, v1);
                float q0 = v0 - __bfloat162float(__low2bfloat16(ph));
                float q1 = v1 - __bfloat162float(__high2bfloat16(ph));
                __nv_bfloat162 pl = __floats2bfloat162_rn(q0, q1);
                *(__nv_bfloat162*)(shi + row * SA + col) = ph;
                *(__nv_bfloat162*)(slo + row * SA + col) = pl;
            }
}

__global__ __launch_bounds__(NTH, 1)
void rnn_mma_kernel(const int* __restrict__ inputs, const float* __restrict__ b2,
                    float* __restrict__ out)
{
    extern __shared__ char smraw[];
    __nv_bfloat16* h1hi = (__nv_bfloat16*)smraw;
    __nv_bfloat16* h1lo = h1hi + 32 * SA;
    __nv_bfloat16* h2hi = h1lo + 32 * SA;
    __nv_bfloat16* h2lo = h2hi + 32 * SA;
    float* b2s  = (float*)(smraw + 67584);
    int*   toks = (int*)(smraw + 68608);

    const int tid = threadIdx.x, lane = tid & 31, w = tid >> 5;
    const int bb = blockIdx.x * M2;
    const u32 smb = smem_u32(smraw);
    const u32 aH1h = smb, aH1l = smb + 16896, aH2h = smb + 33792, aH2l = smb + 50688;

    const int grp = lane >> 3, lr = lane & 7;
    const u32 aoff = (u32)(((lr + (grp & 1) * 8) * SA + (grp >> 1) * 8) * 2);

    for (int i = tid; i < 4 * 32 * SA / 2; i += NTH) ((u32*)h1hi)[i] = 0;
    for (int i = tid; i < H / 4; i += NTH) ((float4*)b2s)[i] = ((const float4*)b2)[i];
    for (int i = tid; i < M2 * T; i += NTH)
        toks[i] = inputs[(bb + i / T) * T + (i % T)];
    __syncthreads();

#pragma unroll 1
    for (int t = 0; t < T; ++t) {
        // ---- layer 1: C = embW[tok] ; C += h1_old @ U1^T ----
        float c[2][4][4];
#pragma unroll
        for (int mt = 0; mt < 2; ++mt)
#pragma unroll
            for (int hv = 0; hv < 2; ++hv) {
                int row = mt * 16 + (lane >> 2) + hv * 8;
                const float* er = g_embW + (size_t)toks[row * T + t] * H;
#pragma unroll
                for (int nt = 0; nt < 4; ++nt) {
                    float2 x = *(const float2*)(er + w * 32 + nt * 8 + (lane & 3) * 2);
                    c[mt][nt][hv * 2] = x.x; c[mt][nt][hv * 2 + 1] = x.y;
                }
            }
        gemm_l1(aH1h, aH1l, c, lane, w, aoff);
        __syncthreads();
        frag_store(c, h1hi, h1lo, lane, w);
        __syncthreads();

        // ---- layer 2 (fused): C = b2 + h1_new @ W2^T + h2_old @ U2^T ----
        float c2[2][4][4];
#pragma unroll
        for (int nt = 0; nt < 4; ++nt) {
            float2 bv = *(const float2*)(b2s + w * 32 + nt * 8 + (lane & 3) * 2);
#pragma unroll
            for (int mt = 0; mt < 2; ++mt) {
                c2[mt][nt][0] = bv.x; c2[mt][nt][1] = bv.y;
                c2[mt][nt][2] = bv.x; c2[mt][nt][3] = bv.y;
            }
        }
        gemm_l2(aH1h, aH1l, aH2h, aH2l, c2, lane, w, aoff);
        __syncthreads();

        if (t == T - 1) {
#pragma unroll
            for (int mt = 0; mt < 2; ++mt)
#pragma unroll
                for (int nt = 0; nt < 4; ++nt)
#pragma unroll
                    for (int hv = 0; hv < 2; ++hv) {
                        int row = mt * 16 + (lane >> 2) + hv * 8;
                        int col = w * 32 + nt * 8 + (lane & 3) * 2;
                        float v0 = tanh_e(c2[mt][nt][hv * 2]);
                        float v1 = tanh_e(c2[mt][nt][hv * 2 + 1]);
                        float2 o;
                        o.x = __fdividef(1.f, 1.f + __expf(-v0));
                        o.y = __fdividef(1.f, 1.f + __expf(-v1));
                        *(float2*)&out[(size_t)(bb + row) * H + col] = o;
                    }
        } else {
            frag_store(c2, h2hi, h2lo, lane, w);
            __syncthreads();
        }
    }
}

extern "C" void kernel_launch(void* const* d_in, const int* in_sizes, int n_in,
                              void* d_out, int out_size)
{
    const int*   inputs = (const int*)  d_in[0];
    const float* emb    = (const float*)d_in[1];
    const float* W1     = (const float*)d_in[2];
    const float* U1     = (const float*)d_in[3];
    const float* b1     = (const float*)d_in[4];
    const float* W2     = (const float*)d_in[5];
    const float* U2     = (const float*)d_in[6];
    const float* b2     = (const float*)d_in[7];
    float* out = (float*)d_out;

    const int smem_embw = (EMB * H + EMB * HS) * (int)sizeof(float);  // 116800
    const int smem_main = 78848;

    cudaFuncSetAttribute(embw_kernel,    cudaFuncAttributeMaxDynamicSharedMemorySize, smem_embw);
    cudaFuncSetAttribute(rnn_mma_kernel, cudaFuncAttributeMaxDynamicSharedMemorySize, smem_main);

    prep_weights<<<(3 * 2 * 8 * 16 * 2 * 32 + 255) / 256, 256>>>(U1, W2, U2);
    embw_kernel<<<(VOCAB + 31) / 32, NTH, smem_embw>>>(emb, W1, b1);
    rnn_mma_kernel<<<BATCH / M2, NTH, smem_main>>>(inputs, b2, out);
}

// round 17
// speedup vs baseline: 4.2822x; 1.3698x over previous
#include <cuda_runtime.h>
#include <cuda_fp16.h>
#include <cstdint>
#include <math.h>

#define BATCH 4096
#define T     80
#define VOCAB 10000
#define EMB   100
#define H     256
#define HS    36
#define M2    32
#define NTH   256
#define SA    264          // state k-stride (fp16): odd 16B-phase -> conflict-free ldmatrix

typedef uint32_t u32; typedef unsigned long long u64;

__device__ float g_embW[(size_t)VOCAB * H];
// B fragments (single fp16 term) in lane order: [gemm][nblock(8)][k16(16)][pair(2)] x [lane(32)][4xu32]
__device__ __align__(16) u32 g_wB[3 * 8 * 16 * 2 * 128];

__device__ __forceinline__ u32 smem_u32(const void* p) {
    u32 a; asm("{ .reg .u64 t; cvta.to.shared.u64 t, %1; cvt.u32.u64 %0, t; }" : "=r"(a) : "l"(p));
    return a;
}
__device__ __forceinline__ float tanh_e(float x) {
    float e = __expf(-2.f * fabsf(x));
    return copysignf(__fdividef(1.f - e, 1.f + e), x);
}
__device__ __forceinline__ u64 ffma2(u64 a, u64 b, u64 c) {
    u64 d; asm("fma.rn.f32x2 %0, %1, %2, %3;" : "=l"(d) : "l"(a), "l"(b), "l"(c)); return d;
}
__device__ __forceinline__ u64 splat2(float x) { u64 d; asm("mov.b64 %0, {%1, %1};" : "=l"(d) : "f"(x)); return d; }
__device__ __forceinline__ u64 pack2(float lo, float hi) { u64 d; asm("mov.b64 %0, {%1, %2};" : "=l"(d) : "f"(lo), "f"(hi)); return d; }
__device__ __forceinline__ void unpack2(u64 p, float& lo, float& hi) { asm("mov.b64 {%0, %1}, %2;" : "=f"(lo), "=f"(hi) : "l"(p)); }

#define LDSM4(r0, r1, r2, r3, a) \
    asm volatile("ldmatrix.sync.aligned.m8n8.x4.shared.b16 {%0,%1,%2,%3}, [%4];" \
                 : "=r"(r0), "=r"(r1), "=r"(r2), "=r"(r3) : "r"(a))
#define MMA(c, a, b0, b1) \
    asm volatile("mma.sync.aligned.m16n8k16.row.col.f32.f16.f16.f32 " \
                 "{%0,%1,%2,%3}, {%4,%5,%6,%7}, {%8,%9}, {%0,%1,%2,%3};" \
                 : "+f"((c)[0]), "+f"((c)[1]), "+f"((c)[2]), "+f"((c)[3]) \
                 : "r"((a)[0]), "r"((a)[1]), "r"((a)[2]), "r"((a)[3]), "r"(b0), "r"(b1))

// ---- prep: weights -> fp16 B-fragments in lane order (layout identical to proven R15 path) ----
__global__ void prep_weights(const float* __restrict__ U1, const float* __restrict__ W2,
                             const float* __restrict__ U2)
{
    int idx = blockIdx.x * blockDim.x + threadIdx.x;
    if (idx >= 3 * 8 * 16 * 2 * 32) return;
    int lane = idx & 31, pr = (idx >> 5) & 1, k16 = (idx >> 6) & 15;
    int nb = (idx >> 10) & 7, g = idx >> 13;
    const float* s = g == 0 ? U1 : g == 1 ? W2 : U2;
    u32 o[4];
#pragma unroll
    for (int j = 0; j < 4; ++j) {
        int nt = pr * 2 + (j >> 1), reg = j & 1;
        int n = nb * 32 + nt * 8 + (lane >> 2);
        int k = k16 * 16 + reg * 8 + (lane & 3) * 2;
        __half2 ph = __floats2half2_rn(s[k * H + n], s[(k + 1) * H + n]);
        o[j] = *(u32*)&ph;
    }
    ((uint4*)g_wB)[idx] = make_uint4(o[0], o[1], o[2], o[3]);
}

// ---- embW = b1 + emb @ W1 (R10-proven, fp32) ----
__global__ __launch_bounds__(NTH, 1)
void embw_kernel(const float* __restrict__ emb, const float* __restrict__ W1,
                 const float* __restrict__ b1)
{
    extern __shared__ float sm[];
    float* W1s = sm; float* xs = W1s + EMB * H;
    const int tid = threadIdx.x, ty = tid >> 6, tx = tid & 63;
    const int r0 = ty * 8, c0 = tx * 4, v0 = blockIdx.x * 32;
#pragma unroll
    for (int j = 0; j < (EMB * H / 4) / NTH; ++j)
        ((float4*)W1s)[tid + j * NTH] = ((const float4*)W1)[tid + j * NTH];
    for (int i = tid; i < EMB * HS; i += NTH) xs[i] = 0.f;
    __syncthreads();
    for (int i = tid; i < 32 * (EMB / 4); i += NTH) {
        int r = i / (EMB / 4), q = i % (EMB / 4), v = v0 + r;
        if (v < VOCAB) {
            float4 x = ((const float4*)emb)[v * (EMB / 4) + q];
            xs[(4 * q + 0) * HS + r] = x.x; xs[(4 * q + 1) * HS + r] = x.y;
            xs[(4 * q + 2) * HS + r] = x.z; xs[(4 * q + 3) * HS + r] = x.w;
        }
    }
    const float4 b1v = ((const float4*)b1)[tx];
    __syncthreads();
    u64 acc[4][4];
    const u64 bp[4] = { splat2(b1v.x), splat2(b1v.y), splat2(b1v.z), splat2(b1v.w) };
#pragma unroll
    for (int p = 0; p < 4; ++p)
#pragma unroll
        for (int j = 0; j < 4; ++j) acc[p][j] = bp[j];
#pragma unroll 4
    for (int k = 0; k < EMB; ++k) {
        float4 a0 = *(const float4*)&xs[k * HS + r0];
        float4 a1 = *(const float4*)&xs[k * HS + r0 + 4];
        float4 b  = *(const float4*)&W1s[k * H + c0];
        u64 ap[4] = { pack2(a0.x, a0.y), pack2(a0.z, a0.w), pack2(a1.x, a1.y), pack2(a1.z, a1.w) };
        u64 bb[4] = { splat2(b.x), splat2(b.y), splat2(b.z), splat2(b.w) };
#pragma unroll
        for (int p = 0; p < 4; ++p)
#pragma unroll
            for (int j = 0; j < 4; ++j) acc[p][j] = ffma2(ap[p], bb[j], acc[p][j]);
    }
#pragma unroll
    for (int i = 0; i < 8; ++i) {
        int v = v0 + r0 + i;
        if (v < VOCAB) {
            float o[4];
#pragma unroll
            for (int j = 0; j < 4; ++j) { float lo, hi; unpack2(acc[i >> 1][j], lo, hi); o[j] = (i & 1) ? hi : lo; }
            *(float4*)&g_embW[(size_t)v * H + c0] = make_float4(o[0], o[1], o[2], o[3]);
        }
    }
}

// load one k16's B fragments (8 u32) for (gemm g, warp nb)
__device__ __forceinline__ void ldB(int g, int nb, int t, int lane, u32 b[8]) {
    const uint4* P = (const uint4*)g_wB;
    int e = (((g * 8 + nb) * 16 + t) * 2) * 32 + lane;
    uint4 v0 = __ldg(&P[e]);
    uint4 v1 = __ldg(&P[e + 32]);
    b[0] = v0.x; b[1] = v0.y; b[2] = v0.z; b[3] = v0.w;
    b[4] = v1.x; b[5] = v1.y; b[6] = v1.z; b[7] = v1.w;
}

// 2-term block: C += Ah@B + Al@B   (A split exact in fp16, B single fp16)
__device__ __forceinline__ void mma_block(float (&c)[2][4][4],
    const u32 ah[8], const u32 al[8], const u32 bh[8])
{
#pragma unroll
    for (int mt = 0; mt < 2; ++mt)
#pragma unroll
        for (int nt = 0; nt < 4; ++nt) {
            float* cc = c[mt][nt];
            MMA(cc, &ah[mt * 4], bh[nt * 2], bh[nt * 2 + 1]);
            MMA(cc, &al[mt * 4], bh[nt * 2], bh[nt * 2 + 1]);
        }
}

// layer-1 GEMM: distance-2 B prefetch
__device__ __forceinline__ void gemm_l1(u32 aHi, u32 aLo,
    float (&c)[2][4][4], int lane, int w, u32 aoff)
{
    u32 bh[2][8];
    ldB(0, w, 0, lane, bh[0]);
    ldB(0, w, 1, lane, bh[1]);
#pragma unroll
    for (int t = 0; t < 16; ++t) {
        u32 kA = (u32)(t * 32);
        u32 ah[8], al[8];
        LDSM4(ah[0], ah[1], ah[2], ah[3], aHi + aoff + kA);
        LDSM4(ah[4], ah[5], ah[6], ah[7], aHi + aoff + 8448 + kA);
        LDSM4(al[0], al[1], al[2], al[3], aLo + aoff + kA);
        LDSM4(al[4], al[5], al[6], al[7], aLo + aoff + 8448 + kA);
        mma_block(c, ah, al, bh[t & 1]);
        if (t + 2 < 16) ldB(0, w, t + 2, lane, bh[t & 1]);
    }
}

// layer-2 fused: C += h1@W2^T + h2@U2^T, one k-loop, distance-1 prefetch of both B's
__device__ __forceinline__ void gemm_l2(u32 a1Hi, u32 a1Lo, u32 a2Hi, u32 a2Lo,
    float (&c)[2][4][4], int lane, int w, u32 aoff)
{
    u32 b1[8], b2[8], n1[8], n2[8];
    ldB(1, w, 0, lane, b1);
    ldB(2, w, 0, lane, b2);
#pragma unroll
    for (int t = 0; t < 16; ++t) {
        if (t < 15) { ldB(1, w, t + 1, lane, n1); ldB(2, w, t + 1, lane, n2); }
        u32 kA = (u32)(t * 32);
        u32 ah[8], al[8];
        LDSM4(ah[0], ah[1], ah[2], ah[3], a1Hi + aoff + kA);
        LDSM4(ah[4], ah[5], ah[6], ah[7], a1Hi + aoff + 8448 + kA);
        LDSM4(al[0], al[1], al[2], al[3], a1Lo + aoff + kA);
        LDSM4(al[4], al[5], al[6], al[7], a1Lo + aoff + 8448 + kA);
        mma_block(c, ah, al, b1);
        LDSM4(ah[0], ah[1], ah[2], ah[3], a2Hi + aoff + kA);
        LDSM4(ah[4], ah[5], ah[6], ah[7], a2Hi + aoff + 8448 + kA);
        LDSM4(al[0], al[1], al[2], al[3], a2Lo + aoff + kA);
        LDSM4(al[4], al[5], al[6], al[7], a2Lo + aoff + 8448 + kA);
        mma_block(c, ah, al, b2);
        if (t < 15) {
#pragma unroll
            for (int q = 0; q < 8; ++q) { b1[q] = n1[q]; b2[q] = n2[q]; }
        }
    }
}

// store tanh'd fragments as fp16 hi + fp16 residual into a state array
__device__ __forceinline__ void frag_store(float (&c)[2][4][4],
    __half* shi, __half* slo, int lane, int w)
{
#pragma unroll
    for (int mt = 0; mt < 2; ++mt)
#pragma unroll
        for (int nt = 0; nt < 4; ++nt)
#pragma unroll
            for (int hv = 0; hv < 2; ++hv) {
                int row = mt * 16 + (lane >> 2) + hv * 8;
                int col = w * 32 + nt * 8 + (lane & 3) * 2;
                float v0 = tanh_e(c[mt][nt][hv * 2]);
                float v1 = tanh_e(c[mt][nt][hv * 2 + 1]);
                __half2 ph = __floats2half2_rn(v0, v1);
                float q0 = v0 - __half2float(__low2half(ph));
                float q1 = v1 - __half2float(__high2half(ph));
                __half2 pl = __floats2half2_rn(q0, q1);
                *(__half2*)(shi + row * SA + col) = ph;
                *(__half2*)(slo + row * SA + col) = pl;
            }
}

__global__ __launch_bounds__(NTH, 1)
void rnn_mma_kernel(const int* __restrict__ inputs, const float* __restrict__ b2,
                    float* __restrict__ out)
{
    extern __shared__ char smraw[];
    __half* h1hi = (__half*)smraw;                 // 32*264*2 = 16896 B each
    __half* h1lo = h1hi + 32 * SA;
    __half* h2hi = h1lo + 32 * SA;
    __half* h2lo = h2hi + 32 * SA;
    float* b2s  = (float*)(smraw + 67584);
    int*   toks = (int*)(smraw + 68608);

    const int tid = threadIdx.x, lane = tid & 31, w = tid >> 5;
    const int bb = blockIdx.x * M2;
    const u32 smb = smem_u32(smraw);
    const u32 aH1h = smb, aH1l = smb + 16896, aH2h = smb + 33792, aH2l = smb + 50688;

    const int grp = lane >> 3, lr = lane & 7;
    const u32 aoff = (u32)(((lr + (grp & 1) * 8) * SA + (grp >> 1) * 8) * 2);

    for (int i = tid; i < 4 * 32 * SA / 2; i += NTH) ((u32*)h1hi)[i] = 0;
    for (int i = tid; i < H / 4; i += NTH) ((float4*)b2s)[i] = ((const float4*)b2)[i];
    for (int i = tid; i < M2 * T; i += NTH)
        toks[i] = inputs[(bb + i / T) * T + (i % T)];
    __syncthreads();

#pragma unroll 1
    for (int t = 0; t < T; ++t) {
        // ---- layer 1: C = embW[tok] ; C += h1_old @ U1^T ----
        float c[2][4][4];
#pragma unroll
        for (int mt = 0; mt < 2; ++mt)
#pragma unroll
            for (int hv = 0; hv < 2; ++hv) {
                int row = mt * 16 + (lane >> 2) + hv * 8;
                const float* er = g_embW + (size_t)toks[row * T + t] * H;
#pragma unroll
                for (int nt = 0; nt < 4; ++nt) {
                    float2 x = *(const float2*)(er + w * 32 + nt * 8 + (lane & 3) * 2);
                    c[mt][nt][hv * 2] = x.x; c[mt][nt][hv * 2 + 1] = x.y;
                }
            }
        gemm_l1(aH1h, aH1l, c, lane, w, aoff);
        __syncthreads();
        frag_store(c, h1hi, h1lo, lane, w);
        __syncthreads();

        // ---- layer 2 (fused): C = b2 + h1_new @ W2^T + h2_old @ U2^T ----
        float c2[2][4][4];
#pragma unroll
        for (int nt = 0; nt < 4; ++nt) {
            float2 bv = *(const float2*)(b2s + w * 32 + nt * 8 + (lane & 3) * 2);
#pragma unroll
            for (int mt = 0; mt < 2; ++mt) {
                c2[mt][nt][0] = bv.x; c2[mt][nt][1] = bv.y;
                c2[mt][nt][2] = bv.x; c2[mt][nt][3] = bv.y;
            }
        }
        gemm_l2(aH1h, aH1l, aH2h, aH2l, c2, lane, w, aoff);
        __syncthreads();

        if (t == T - 1) {
#pragma unroll
            for (int mt = 0; mt < 2; ++mt)
#pragma unroll
                for (int nt = 0; nt < 4; ++nt)
#pragma unroll
                    for (int hv = 0; hv < 2; ++hv) {
                        int row = mt * 16 + (lane >> 2) + hv * 8;
                        int col = w * 32 + nt * 8 + (lane & 3) * 2;
                        float v0 = tanh_e(c2[mt][nt][hv * 2]);
                        float v1 = tanh_e(c2[mt][nt][hv * 2 + 1]);
                        float2 o;
                        o.x = __fdividef(1.f, 1.f + __expf(-v0));
                        o.y = __fdividef(1.f, 1.f + __expf(-v1));
                        *(float2*)&out[(size_t)(bb + row) * H + col] = o;
                    }
        } else {
            frag_store(c2, h2hi, h2lo, lane, w);
            __syncthreads();
        }
    }
}

extern "C" void kernel_launch(void* const* d_in, const int* in_sizes, int n_in,
                              void* d_out, int out_size)
{
    const int*   inputs = (const int*)  d_in[0];
    const float* emb    = (const float*)d_in[1];
    const float* W1     = (const float*)d_in[2];
    const float* U1     = (const float*)d_in[3];
    const float* b1     = (const float*)d_in[4];
    const float* W2     = (const float*)d_in[5];
    const float* U2     = (const float*)d_in[6];
    const float* b2     = (const float*)d_in[7];
    float* out = (float*)d_out;

    const int smem_embw = (EMB * H + EMB * HS) * (int)sizeof(float);  // 116800
    const int smem_main = 78848;

    cudaFuncSetAttribute(embw_kernel,    cudaFuncAttributeMaxDynamicSharedMemorySize, smem_embw);
    cudaFuncSetAttribute(rnn_mma_kernel, cudaFuncAttributeMaxDynamicSharedMemorySize, smem_main);

    prep_weights<<<(3 * 8 * 16 * 2 * 32 + 255) / 256, 256>>>(U1, W2, U2);
    embw_kernel<<<(VOCAB + 31) / 32, NTH, smem_embw>>>(emb, W1, b1);
    rnn_mma_kernel<<<BATCH / M2, NTH, smem_main>>>(inputs, b2, out);
}